// round 8
// baseline (speedup 1.0000x reference)
#include <cuda_runtime.h>
#include <cstdint>
#include <cstddef>

namespace {

constexpr int PAD_ID  = 72;     // VOCAB
constexpr int NB_MAIN = 592;    // 4 CTAs/SM * 148 SMs
constexpr int CTX_SEG = 128;    // tokens scanned per ctx block

// warp LayerNorm stats over 256 values (8 per lane)
__device__ __forceinline__ void warp_ln(const float* h, float& mu, float& rs)
{
    float s1 = 0.f, s2 = 0.f;
#pragma unroll
    for (int k = 0; k < 8; ++k) { s1 += h[k]; s2 = fmaf(h[k], h[k], s2); }
#pragma unroll
    for (int o = 16; o; o >>= 1) {
        s1 += __shfl_xor_sync(0xffffffffu, s1, o);
        s2 += __shfl_xor_sync(0xffffffffu, s2, o);
    }
    mu = s1 * (1.f / 256.f);
    float var = s2 * (1.f / 256.f) - mu * mu;
    rs = rsqrtf(var + 1e-5f);
}

// ======================= main kernel (everything except ctx MLP) =======================
__global__ __launch_bounds__(256, 4) void poker_main_kernel(
    const int*   __restrict__ token_ids,
    const int*   __restrict__ token_streets,
    const int*   __restrict__ card_ranks,
    const int*   __restrict__ card_suits,
    const int*   __restrict__ action_actors,
    const float* __restrict__ legal_masks,   // [T,16]
    const float* __restrict__ cf,            // [T,9]
    const float* __restrict__ base_emb,      // [73,256]
    const float* __restrict__ street_emb,    // [4,256]
    const float* __restrict__ rank_emb,      // [13,256]
    const float* __restrict__ suit_emb,      // [4,256]
    const float* __restrict__ actor_emb,     // [2,256]
    const float* __restrict__ atype_emb,     // [16,256]
    const float* __restrict__ legal_W,       // [256,16]
    const float* __restrict__ legal_b,
    const float* __restrict__ legal_g,
    const float* __restrict__ legal_be,
    const float* __restrict__ game_W,        // [256,5]
    const float* __restrict__ game_b,
    const float* __restrict__ game_g,
    const float* __restrict__ game_be,
    float*       __restrict__ out,           // [T,256]
    int tokens)
{
    __shared__ float4 s_W[1024];        // swizzled legal_W (16 KB)

    const int tid  = threadIdx.x;
    const int lane = tid & 31;
    const int wid  = tid >> 5;

    {
        const float4* Wg = reinterpret_cast<const float4*>(legal_W);
        for (int q = tid; q < 1024; q += 256)
            s_W[q ^ ((q >> 5) & 7)] = Wg[q];
    }
    __syncthreads();   // the ONLY block barrier

    const int gwarp  = blockIdx.x * 8 + wid;
    const int nwarp  = gridDim.x * 8;
    const int l8     = lane << 3;
    const int swbase = (lane << 5);
    const int swxor  = lane & 7;

    // software pipeline: metadata for the current token is loaded one iteration ahead
    int t   = gwarp;
    int raw = 0, st = 0;
    if (t < tokens) {
        raw = __ldg(token_ids + t);
        st  = __ldg(token_streets + t);
    }

    while (t < tokens) {
        // prefetch next token's metadata (heads the next iteration's dependency chain)
        const int tn = t + nwarp;
        int raw_n = 0, st_n = 0;
        if (tn < tokens) {
            raw_n = __ldg(token_ids + tn);
            st_n  = __ldg(token_streets + tn);
        }

        const bool pad = raw < 0;
        const int  id  = pad ? PAD_ID : raw;

        float ar[8];
        {
            const float4* bp = reinterpret_cast<const float4*>(base_emb)   + id * 64 + lane * 2;
            const float4* sp = reinterpret_cast<const float4*>(street_emb) + st * 64 + lane * 2;
            const float4 b0 = __ldg(bp), b1 = __ldg(bp + 1);
            const float4 s0 = __ldg(sp), s1 = __ldg(sp + 1);
            ar[0] = b0.x + s0.x; ar[1] = b0.y + s0.y; ar[2] = b0.z + s0.z; ar[3] = b0.w + s0.w;
            ar[4] = b1.x + s1.x; ar[5] = b1.y + s1.y; ar[6] = b1.z + s1.z; ar[7] = b1.w + s1.w;
        }

        if (id >= 4 && id < 56) {
            // ---- card token ----
            int rk = __ldg(card_ranks + t); rk = rk < 0 ? 0 : (rk > 12 ? 12 : rk);
            int su = __ldg(card_suits + t); su = su < 0 ? 0 : (su > 3  ? 3  : su);
            const float4* rp = reinterpret_cast<const float4*>(rank_emb) + rk * 64 + lane * 2;
            const float4* up = reinterpret_cast<const float4*>(suit_emb) + su * 64 + lane * 2;
            const float4 r0 = __ldg(rp), r1 = __ldg(rp + 1);
            const float4 u0 = __ldg(up), u1 = __ldg(up + 1);
            ar[0] += r0.x + u0.x; ar[1] += r0.y + u0.y; ar[2] += r0.z + u0.z; ar[3] += r0.w + u0.w;
            ar[4] += r1.x + u1.x; ar[5] += r1.y + u1.y; ar[6] += r1.z + u1.z; ar[7] += r1.w + u1.w;
        } else if (id >= 56 && id < 72) {
            // ---- action token ----
            int ac = __ldg(action_actors + t); ac = ac < 0 ? 0 : (ac > 1 ? 1 : ac);
            const float4* ap = reinterpret_cast<const float4*>(actor_emb) + ac * 64 + lane * 2;
            const float4* tp = reinterpret_cast<const float4*>(atype_emb) + (id - 56) * 64 + lane * 2;
            const float4 a0 = __ldg(ap), a1 = __ldg(ap + 1);
            const float4 y0 = __ldg(tp), y1 = __ldg(tp + 1);
            ar[0] += a0.x + y0.x; ar[1] += a0.y + y0.y; ar[2] += a0.z + y0.z; ar[3] += a0.w + y0.w;
            ar[4] += a1.x + y1.x; ar[5] += a1.y + y1.y; ar[6] += a1.z + y1.z; ar[7] += a1.w + y1.w;

            const float4* xp = reinterpret_cast<const float4*>(legal_masks) + (size_t)t * 4;
            const float4 x0 = __ldg(xp), x1 = __ldg(xp + 1), x2 = __ldg(xp + 2), x3 = __ldg(xp + 3);

            float h[8];
            {
                const float4* bbp = reinterpret_cast<const float4*>(legal_b) + lane * 2;
                const float4 hb0 = __ldg(bbp), hb1 = __ldg(bbp + 1);
                h[0]=hb0.x; h[1]=hb0.y; h[2]=hb0.z; h[3]=hb0.w;
                h[4]=hb1.x; h[5]=hb1.y; h[6]=hb1.z; h[7]=hb1.w;
            }
#pragma unroll
            for (int kk = 0; kk < 8; ++kk) {
                float4 w;
                w = s_W[swbase + (((kk << 2) | 0) ^ swxor)];
                h[kk] = fmaf(w.x, x0.x, h[kk]); h[kk] = fmaf(w.y, x0.y, h[kk]);
                h[kk] = fmaf(w.z, x0.z, h[kk]); h[kk] = fmaf(w.w, x0.w, h[kk]);
                w = s_W[swbase + (((kk << 2) | 1) ^ swxor)];
                h[kk] = fmaf(w.x, x1.x, h[kk]); h[kk] = fmaf(w.y, x1.y, h[kk]);
                h[kk] = fmaf(w.z, x1.z, h[kk]); h[kk] = fmaf(w.w, x1.w, h[kk]);
                w = s_W[swbase + (((kk << 2) | 2) ^ swxor)];
                h[kk] = fmaf(w.x, x2.x, h[kk]); h[kk] = fmaf(w.y, x2.y, h[kk]);
                h[kk] = fmaf(w.z, x2.z, h[kk]); h[kk] = fmaf(w.w, x2.w, h[kk]);
                w = s_W[swbase + (((kk << 2) | 3) ^ swxor)];
                h[kk] = fmaf(w.x, x3.x, h[kk]); h[kk] = fmaf(w.y, x3.y, h[kk]);
                h[kk] = fmaf(w.z, x3.z, h[kk]); h[kk] = fmaf(w.w, x3.w, h[kk]);
            }
            float mu, rs;
            warp_ln(h, mu, rs);
            const float4* gp = reinterpret_cast<const float4*>(legal_g)  + lane * 2;
            const float4* ep = reinterpret_cast<const float4*>(legal_be) + lane * 2;
            const float4 g0 = __ldg(gp), g1 = __ldg(gp + 1);
            const float4 e0 = __ldg(ep), e1 = __ldg(ep + 1);
            const float gg[8] = {g0.x,g0.y,g0.z,g0.w,g1.x,g1.y,g1.z,g1.w};
            const float ee[8] = {e0.x,e0.y,e0.z,e0.w,e1.x,e1.y,e1.z,e1.w};
#pragma unroll
            for (int kk = 0; kk < 8; ++kk) {
                const float v = fmaf((h[kk] - mu) * rs, gg[kk], ee[kk]);
                ar[kk] += fmaxf(v, 0.f);
            }
        }

        // ---- game MLP: sequence position 0 only (256 occurrences total) ----
        if ((t & 511) == 0) {
            const int n = t >> 9;
            const float* c0 = cf + (size_t)n * 512 * 9;
            const float sb = __ldg(c0), bb = __ldg(c0 + 1), po = __ldg(c0 + 2);
            const float scale = 100.f * bb;
            const float ssg = (scale == 0.f) ? 1e-8f : scale;
            const float f3 = bb / ssg, f4 = sb / ssg;
            float h[8];
            {
                const float4* bbp = reinterpret_cast<const float4*>(game_b) + lane * 2;
                const float4 hb0 = __ldg(bbp), hb1 = __ldg(bbp + 1);
                h[0]=hb0.x; h[1]=hb0.y; h[2]=hb0.z; h[3]=hb0.w;
                h[4]=hb1.x; h[5]=hb1.y; h[6]=hb1.z; h[7]=hb1.w;
            }
#pragma unroll
            for (int kk = 0; kk < 8; ++kk) {
                const float* wr = game_W + (size_t)(l8 + kk) * 5;
                float s = h[kk];
                s = fmaf(__ldg(wr + 0), sb, s);
                s = fmaf(__ldg(wr + 1), bb, s);
                s = fmaf(__ldg(wr + 2), po, s);
                s = fmaf(__ldg(wr + 3), f3, s);
                s = fmaf(__ldg(wr + 4), f4, s);
                h[kk] = s;
            }
            float mu, rs;
            warp_ln(h, mu, rs);
            const float4* gp = reinterpret_cast<const float4*>(game_g)  + lane * 2;
            const float4* ep = reinterpret_cast<const float4*>(game_be) + lane * 2;
            const float4 g0 = __ldg(gp), g1 = __ldg(gp + 1);
            const float4 e0 = __ldg(ep), e1 = __ldg(ep + 1);
            const float gg[8] = {g0.x,g0.y,g0.z,g0.w,g1.x,g1.y,g1.z,g1.w};
            const float ee[8] = {e0.x,e0.y,e0.z,e0.w,e1.x,e1.y,e1.z,e1.w};
#pragma unroll
            for (int kk = 0; kk < 8; ++kk) {
                const float v = fmaf((h[kk] - mu) * rs, gg[kk], ee[kk]);
                ar[kk] += fmaxf(v, 0.f);
            }
        }

        // ---- store (pad -> 0), vectorized ----
        float4 o0, o1;
        if (pad) {
            o0 = make_float4(0.f, 0.f, 0.f, 0.f);
            o1 = o0;
        } else {
            o0 = make_float4(ar[0], ar[1], ar[2], ar[3]);
            o1 = make_float4(ar[4], ar[5], ar[6], ar[7]);
        }
        float4* op = reinterpret_cast<float4*>(out) + (size_t)t * 64 + lane * 2;
        op[0] = o0;
        op[1] = o1;

        t = tn; raw = raw_n; st = st_n;
    }
}

// ======================= ctx kernel: scan segment, block per match =======================
__global__ __launch_bounds__(256, 8) void poker_ctx_kernel(
    const int*   __restrict__ token_ids,
    const float* __restrict__ cf,            // [T,9]
    const float* __restrict__ ctx_W,         // [256,143]
    const float* __restrict__ ctx_b,
    const float* __restrict__ ctx_g,
    const float* __restrict__ ctx_be,
    float*       __restrict__ out,           // [T,256]
    int tokens)
{
    __shared__ float s_ca[160];
    __shared__ float s_red[16];
    __shared__ float s_ms[2];
    __shared__ int   s_list[CTX_SEG];
    __shared__ int   s_cnt;

    const int tid  = threadIdx.x;
    const int lane = tid & 31;
    const int wid  = tid >> 5;

    // ---- scan this block's segment for ctx tokens (id == 1) ----
    const int s0 = blockIdx.x * CTX_SEG;
    const int e0 = (s0 + CTX_SEG < tokens) ? s0 + CTX_SEG : tokens;
    if (tid == 0) s_cnt = 0;
    __syncthreads();
    if (s0 + tid < e0) {
        if (__ldg(token_ids + s0 + tid) == 1) {
            const int k = atomicAdd(&s_cnt, 1);
            s_list[k] = s0 + tid;
        }
    }
    __syncthreads();
    const int m = s_cnt;

    for (int g = 0; g < m; ++g) {
        __syncthreads();                    // smem reuse guard
        const int t = s_list[g];
        const int n = t >> 9;

        // ---- p[13] -> ctx_all[143] ----
        if (tid < 143) {
            const float* c0 = cf + (size_t)n * 512 * 9;
            const float* cp = cf + (size_t)t * 9;
            const float bb = __ldg(c0 + 1);
            const float scale = 100.f * bb;
            const float ssafe   = (scale == 0.f) ? 1.f : scale;
            const float bbsafe  = (bb == 0.f) ? 1.f : bb;
            const float pot     = __ldg(cp);
            const float potsafe = (pot == 0.f) ? 1.f : pot;
            const int fi = tid / 11;
            const int ps = tid - fi * 11;
            const int si = (fi < 9) ? fi : ((fi < 11) ? fi - 8 : fi - 10);
            const float num = __ldg(cp + si);
            float den = ssafe;
            if (fi == 5 || fi == 6)       den = 1.f;
            else if (fi == 9 || fi == 10) den = bbsafe;
            else if (fi >= 11)            den = potsafe;
            const float pv = num / den;
            float val;
            if (ps == 0)      val = pv;
            else if (ps <= 5) val = sinpif(pv * (float)(1 << (ps - 1)));
            else              val = cospif(pv * (float)(1 << (ps - 6)));
            s_ca[tid] = val;
        }
        __syncthreads();

        // ---- dot products: warp w owns dims [w*32, w*32+32) ----
        const float ca0 = s_ca[lane];
        const float ca1 = s_ca[lane + 32];
        const float ca2 = s_ca[lane + 64];
        const float ca3 = s_ca[lane + 96];
        const float ca4 = (lane < 15) ? s_ca[lane + 128] : 0.f;
        float h = __ldg(ctx_b + tid);
#pragma unroll 4
        for (int c = 0; c < 32; ++c) {
            const float* wr = ctx_W + (size_t)(wid * 32 + c) * 143;
            float sum = ca0 * __ldg(wr + lane)
                      + ca1 * __ldg(wr + lane + 32)
                      + ca2 * __ldg(wr + lane + 64)
                      + ca3 * __ldg(wr + lane + 96);
            if (lane < 15) sum = fmaf(ca4, __ldg(wr + lane + 128), sum);
#pragma unroll
            for (int o = 16; o; o >>= 1)
                sum += __shfl_xor_sync(0xffffffffu, sum, o);
            if (lane == c) h += sum;
        }

        // ---- block LayerNorm over 256 dims ----
        float s1 = h, s2 = h * h;
#pragma unroll
        for (int o = 16; o; o >>= 1) {
            s1 += __shfl_xor_sync(0xffffffffu, s1, o);
            s2 += __shfl_xor_sync(0xffffffffu, s2, o);
        }
        if (lane == 0) { s_red[wid * 2] = s1; s_red[wid * 2 + 1] = s2; }
        __syncthreads();
        if (tid == 0) {
            float t1 = 0.f, t2 = 0.f;
#pragma unroll
            for (int w = 0; w < 8; ++w) { t1 += s_red[w * 2]; t2 += s_red[w * 2 + 1]; }
            const float mu  = t1 * (1.f / 256.f);
            const float var = t2 * (1.f / 256.f) - mu * mu;
            s_ms[0] = mu;
            s_ms[1] = rsqrtf(var + 1e-5f);
        }
        __syncthreads();
        const float v = fmaf((h - s_ms[0]) * s_ms[1], __ldg(ctx_g + tid), __ldg(ctx_be + tid));
        out[(size_t)t * 256 + tid] += fmaxf(v, 0.f);
    }
}

} // namespace

extern "C" void kernel_launch(void* const* d_in, const int* in_sizes, int n_in,
                              void* d_out, int out_size)
{
    const int tokens = in_sizes[0];   // N*S

    poker_main_kernel<<<NB_MAIN, 256>>>(
        (const int*)  d_in[0],   // token_ids
        (const int*)  d_in[1],   // token_streets
        (const int*)  d_in[2],   // card_ranks
        (const int*)  d_in[3],   // card_suits
        (const int*)  d_in[4],   // action_actors
        (const float*)d_in[5],   // action_legal_masks
        (const float*)d_in[6],   // context_features
        (const float*)d_in[7],   // base_emb
        (const float*)d_in[8],   // street_emb
        (const float*)d_in[9],   // rank_emb
        (const float*)d_in[10],  // suit_emb
        (const float*)d_in[11],  // actor_emb
        (const float*)d_in[12],  // atype_emb
        (const float*)d_in[13],  // legal_W
        (const float*)d_in[14],  // legal_b
        (const float*)d_in[15],  // legal_g
        (const float*)d_in[16],  // legal_beta
        (const float*)d_in[17],  // game_W
        (const float*)d_in[18],  // game_b
        (const float*)d_in[19],  // game_g
        (const float*)d_in[20],  // game_beta
        (float*)d_out,
        tokens);

    const int nb_ctx = (tokens + CTX_SEG - 1) / CTX_SEG;
    poker_ctx_kernel<<<nb_ctx, 256>>>(
        (const int*)  d_in[0],   // token_ids
        (const float*)d_in[6],   // context_features
        (const float*)d_in[21],  // ctx_W
        (const float*)d_in[22],  // ctx_b
        (const float*)d_in[23],  // ctx_g
        (const float*)d_in[24],  // ctx_beta
        (float*)d_out,
        tokens);
}

// round 9
// speedup vs baseline: 1.4450x; 1.4450x over previous
#include <cuda_runtime.h>
#include <cstdint>
#include <cstddef>

namespace {

constexpr int PAD_ID  = 72;     // VOCAB
constexpr int NB_MAIN = 592;    // 4 CTAs/SM * 148 SMs
constexpr int CTX_SEG = 64;     // tokens scanned per ctx block

// ctx_W transposed: g_Wt[k][d] = ctx_W[d][k]  (143 x 256 = 146 KB, L1-resident)
__device__ float g_Wt[143 * 256];

__global__ __launch_bounds__(256) void transpose_ctx_kernel(const float* __restrict__ ctx_W)
{
    const int e = blockIdx.x * 256 + threadIdx.x;   // e = k*256 + d
    if (e < 143 * 256) {
        const int k = e >> 8;
        const int d = e & 255;
        g_Wt[e] = __ldg(ctx_W + d * 143 + k);
    }
}

// warp LayerNorm stats over 256 values (8 per lane)
__device__ __forceinline__ void warp_ln(const float* h, float& mu, float& rs)
{
    float s1 = 0.f, s2 = 0.f;
#pragma unroll
    for (int k = 0; k < 8; ++k) { s1 += h[k]; s2 = fmaf(h[k], h[k], s2); }
#pragma unroll
    for (int o = 16; o; o >>= 1) {
        s1 += __shfl_xor_sync(0xffffffffu, s1, o);
        s2 += __shfl_xor_sync(0xffffffffu, s2, o);
    }
    mu = s1 * (1.f / 256.f);
    float var = s2 * (1.f / 256.f) - mu * mu;
    rs = rsqrtf(var + 1e-5f);
}

// ======================= main kernel (everything except ctx MLP) =======================
__global__ __launch_bounds__(256, 4) void poker_main_kernel(
    const int*   __restrict__ token_ids,
    const int*   __restrict__ token_streets,
    const int*   __restrict__ card_ranks,
    const int*   __restrict__ card_suits,
    const int*   __restrict__ action_actors,
    const float* __restrict__ legal_masks,   // [T,16]
    const float* __restrict__ cf,            // [T,9]
    const float* __restrict__ base_emb,      // [73,256]
    const float* __restrict__ street_emb,    // [4,256]
    const float* __restrict__ rank_emb,      // [13,256]
    const float* __restrict__ suit_emb,      // [4,256]
    const float* __restrict__ actor_emb,     // [2,256]
    const float* __restrict__ atype_emb,     // [16,256]
    const float* __restrict__ legal_W,       // [256,16]
    const float* __restrict__ legal_b,
    const float* __restrict__ legal_g,
    const float* __restrict__ legal_be,
    const float* __restrict__ game_W,        // [256,5]
    const float* __restrict__ game_b,
    const float* __restrict__ game_g,
    const float* __restrict__ game_be,
    float*       __restrict__ out,           // [T,256]
    int tokens)
{
    __shared__ float4 s_W[1024];        // swizzled legal_W (16 KB)

    const int tid  = threadIdx.x;
    const int lane = tid & 31;
    const int wid  = tid >> 5;

    {
        const float4* Wg = reinterpret_cast<const float4*>(legal_W);
        for (int q = tid; q < 1024; q += 256)
            s_W[q ^ ((q >> 5) & 7)] = Wg[q];
    }
    __syncthreads();   // the ONLY block barrier

    const int gwarp  = blockIdx.x * 8 + wid;
    const int nwarp  = gridDim.x * 8;
    const int l8     = lane << 3;
    const int swbase = (lane << 5);
    const int swxor  = lane & 7;

    // software pipeline: metadata for the current token is loaded one iteration ahead
    int t   = gwarp;
    int raw = 0, st = 0;
    if (t < tokens) {
        raw = __ldg(token_ids + t);
        st  = __ldg(token_streets + t);
    }

    while (t < tokens) {
        const int tn = t + nwarp;
        int raw_n = 0, st_n = 0;
        if (tn < tokens) {
            raw_n = __ldg(token_ids + tn);
            st_n  = __ldg(token_streets + tn);
        }

        const bool pad = raw < 0;
        const int  id  = pad ? PAD_ID : raw;

        float ar[8];
        {
            const float4* bp = reinterpret_cast<const float4*>(base_emb)   + id * 64 + lane * 2;
            const float4* sp = reinterpret_cast<const float4*>(street_emb) + st * 64 + lane * 2;
            const float4 b0 = __ldg(bp), b1 = __ldg(bp + 1);
            const float4 s0 = __ldg(sp), s1 = __ldg(sp + 1);
            ar[0] = b0.x + s0.x; ar[1] = b0.y + s0.y; ar[2] = b0.z + s0.z; ar[3] = b0.w + s0.w;
            ar[4] = b1.x + s1.x; ar[5] = b1.y + s1.y; ar[6] = b1.z + s1.z; ar[7] = b1.w + s1.w;
        }

        if (id >= 4 && id < 56) {
            // ---- card token ----
            int rk = __ldg(card_ranks + t); rk = rk < 0 ? 0 : (rk > 12 ? 12 : rk);
            int su = __ldg(card_suits + t); su = su < 0 ? 0 : (su > 3  ? 3  : su);
            const float4* rp = reinterpret_cast<const float4*>(rank_emb) + rk * 64 + lane * 2;
            const float4* up = reinterpret_cast<const float4*>(suit_emb) + su * 64 + lane * 2;
            const float4 r0 = __ldg(rp), r1 = __ldg(rp + 1);
            const float4 u0 = __ldg(up), u1 = __ldg(up + 1);
            ar[0] += r0.x + u0.x; ar[1] += r0.y + u0.y; ar[2] += r0.z + u0.z; ar[3] += r0.w + u0.w;
            ar[4] += r1.x + u1.x; ar[5] += r1.y + u1.y; ar[6] += r1.z + u1.z; ar[7] += r1.w + u1.w;
        } else if (id >= 56 && id < 72) {
            // ---- action token ----
            int ac = __ldg(action_actors + t); ac = ac < 0 ? 0 : (ac > 1 ? 1 : ac);
            const float4* ap = reinterpret_cast<const float4*>(actor_emb) + ac * 64 + lane * 2;
            const float4* tp = reinterpret_cast<const float4*>(atype_emb) + (id - 56) * 64 + lane * 2;
            const float4 a0 = __ldg(ap), a1 = __ldg(ap + 1);
            const float4 y0 = __ldg(tp), y1 = __ldg(tp + 1);
            ar[0] += a0.x + y0.x; ar[1] += a0.y + y0.y; ar[2] += a0.z + y0.z; ar[3] += a0.w + y0.w;
            ar[4] += a1.x + y1.x; ar[5] += a1.y + y1.y; ar[6] += a1.z + y1.z; ar[7] += a1.w + y1.w;

            const float4* xp = reinterpret_cast<const float4*>(legal_masks) + (size_t)t * 4;
            const float4 x0 = __ldg(xp), x1 = __ldg(xp + 1), x2 = __ldg(xp + 2), x3 = __ldg(xp + 3);

            float h[8];
            {
                const float4* bbp = reinterpret_cast<const float4*>(legal_b) + lane * 2;
                const float4 hb0 = __ldg(bbp), hb1 = __ldg(bbp + 1);
                h[0]=hb0.x; h[1]=hb0.y; h[2]=hb0.z; h[3]=hb0.w;
                h[4]=hb1.x; h[5]=hb1.y; h[6]=hb1.z; h[7]=hb1.w;
            }
#pragma unroll
            for (int kk = 0; kk < 8; ++kk) {
                float4 w;
                w = s_W[swbase + (((kk << 2) | 0) ^ swxor)];
                h[kk] = fmaf(w.x, x0.x, h[kk]); h[kk] = fmaf(w.y, x0.y, h[kk]);
                h[kk] = fmaf(w.z, x0.z, h[kk]); h[kk] = fmaf(w.w, x0.w, h[kk]);
                w = s_W[swbase + (((kk << 2) | 1) ^ swxor)];
                h[kk] = fmaf(w.x, x1.x, h[kk]); h[kk] = fmaf(w.y, x1.y, h[kk]);
                h[kk] = fmaf(w.z, x1.z, h[kk]); h[kk] = fmaf(w.w, x1.w, h[kk]);
                w = s_W[swbase + (((kk << 2) | 2) ^ swxor)];
                h[kk] = fmaf(w.x, x2.x, h[kk]); h[kk] = fmaf(w.y, x2.y, h[kk]);
                h[kk] = fmaf(w.z, x2.z, h[kk]); h[kk] = fmaf(w.w, x2.w, h[kk]);
                w = s_W[swbase + (((kk << 2) | 3) ^ swxor)];
                h[kk] = fmaf(w.x, x3.x, h[kk]); h[kk] = fmaf(w.y, x3.y, h[kk]);
                h[kk] = fmaf(w.z, x3.z, h[kk]); h[kk] = fmaf(w.w, x3.w, h[kk]);
            }
            float mu, rs;
            warp_ln(h, mu, rs);
            const float4* gp = reinterpret_cast<const float4*>(legal_g)  + lane * 2;
            const float4* ep = reinterpret_cast<const float4*>(legal_be) + lane * 2;
            const float4 g0 = __ldg(gp), g1 = __ldg(gp + 1);
            const float4 e0 = __ldg(ep), e1 = __ldg(ep + 1);
            const float gg[8] = {g0.x,g0.y,g0.z,g0.w,g1.x,g1.y,g1.z,g1.w};
            const float ee[8] = {e0.x,e0.y,e0.z,e0.w,e1.x,e1.y,e1.z,e1.w};
#pragma unroll
            for (int kk = 0; kk < 8; ++kk) {
                const float v = fmaf((h[kk] - mu) * rs, gg[kk], ee[kk]);
                ar[kk] += fmaxf(v, 0.f);
            }
        }

        // ---- game MLP: sequence position 0 only (256 occurrences total) ----
        if ((t & 511) == 0) {
            const int n = t >> 9;
            const float* c0 = cf + (size_t)n * 512 * 9;
            const float sb = __ldg(c0), bb = __ldg(c0 + 1), po = __ldg(c0 + 2);
            const float scale = 100.f * bb;
            const float ssg = (scale == 0.f) ? 1e-8f : scale;
            const float f3 = bb / ssg, f4 = sb / ssg;
            float h[8];
            {
                const float4* bbp = reinterpret_cast<const float4*>(game_b) + lane * 2;
                const float4 hb0 = __ldg(bbp), hb1 = __ldg(bbp + 1);
                h[0]=hb0.x; h[1]=hb0.y; h[2]=hb0.z; h[3]=hb0.w;
                h[4]=hb1.x; h[5]=hb1.y; h[6]=hb1.z; h[7]=hb1.w;
            }
#pragma unroll
            for (int kk = 0; kk < 8; ++kk) {
                const float* wr = game_W + (size_t)(l8 + kk) * 5;
                float s = h[kk];
                s = fmaf(__ldg(wr + 0), sb, s);
                s = fmaf(__ldg(wr + 1), bb, s);
                s = fmaf(__ldg(wr + 2), po, s);
                s = fmaf(__ldg(wr + 3), f3, s);
                s = fmaf(__ldg(wr + 4), f4, s);
                h[kk] = s;
            }
            float mu, rs;
            warp_ln(h, mu, rs);
            const float4* gp = reinterpret_cast<const float4*>(game_g)  + lane * 2;
            const float4* ep = reinterpret_cast<const float4*>(game_be) + lane * 2;
            const float4 g0 = __ldg(gp), g1 = __ldg(gp + 1);
            const float4 e0 = __ldg(ep), e1 = __ldg(ep + 1);
            const float gg[8] = {g0.x,g0.y,g0.z,g0.w,g1.x,g1.y,g1.z,g1.w};
            const float ee[8] = {e0.x,e0.y,e0.z,e0.w,e1.x,e1.y,e1.z,e1.w};
#pragma unroll
            for (int kk = 0; kk < 8; ++kk) {
                const float v = fmaf((h[kk] - mu) * rs, gg[kk], ee[kk]);
                ar[kk] += fmaxf(v, 0.f);
            }
        }

        // ---- store (pad -> 0), vectorized ----
        float4 o0, o1;
        if (pad) {
            o0 = make_float4(0.f, 0.f, 0.f, 0.f);
            o1 = o0;
        } else {
            o0 = make_float4(ar[0], ar[1], ar[2], ar[3]);
            o1 = make_float4(ar[4], ar[5], ar[6], ar[7]);
        }
        float4* op = reinterpret_cast<float4*>(out) + (size_t)t * 64 + lane * 2;
        op[0] = o0;
        op[1] = o1;

        t = tn; raw = raw_n; st = st_n;
    }
}

// ======================= ctx kernel: scan segment, thread-owns-dim dot =======================
__global__ __launch_bounds__(256, 8) void poker_ctx_kernel(
    const int*   __restrict__ token_ids,
    const float* __restrict__ cf,            // [T,9]
    const float* __restrict__ ctx_b,
    const float* __restrict__ ctx_g,
    const float* __restrict__ ctx_be,
    float*       __restrict__ out,           // [T,256]
    int tokens)
{
    __shared__ float s_ca[144];
    __shared__ float s_red[16];
    __shared__ float s_ms[2];
    __shared__ int   s_list[CTX_SEG];
    __shared__ int   s_cnt;

    const int tid  = threadIdx.x;
    const int lane = tid & 31;
    const int wid  = tid >> 5;

    // ---- scan this block's segment for ctx tokens (id == 1) ----
    const int s0 = blockIdx.x * CTX_SEG;
    const int e0 = (s0 + CTX_SEG < tokens) ? s0 + CTX_SEG : tokens;
    if (tid == 0) s_cnt = 0;
    __syncthreads();
    if (tid < CTX_SEG && s0 + tid < e0) {
        if (__ldg(token_ids + s0 + tid) == 1) {
            const int k = atomicAdd(&s_cnt, 1);
            s_list[k] = s0 + tid;
        }
    }
    __syncthreads();
    const int m = s_cnt;

    for (int g = 0; g < m; ++g) {
        __syncthreads();                    // smem reuse guard
        const int t = s_list[g];
        const int n = t >> 9;

        // ---- p[13] -> ctx_all[143] ----
        if (tid < 143) {
            const float* c0 = cf + (size_t)n * 512 * 9;
            const float* cp = cf + (size_t)t * 9;
            const float bb = __ldg(c0 + 1);
            const float scale = 100.f * bb;
            const float ssafe   = (scale == 0.f) ? 1.f : scale;
            const float bbsafe  = (bb == 0.f) ? 1.f : bb;
            const float pot     = __ldg(cp);
            const float potsafe = (pot == 0.f) ? 1.f : pot;
            const int fi = tid / 11;
            const int ps = tid - fi * 11;
            const int si = (fi < 9) ? fi : ((fi < 11) ? fi - 8 : fi - 10);
            const float num = __ldg(cp + si);
            float den = ssafe;
            if (fi == 5 || fi == 6)       den = 1.f;
            else if (fi == 9 || fi == 10) den = bbsafe;
            else if (fi >= 11)            den = potsafe;
            const float pv = num / den;
            float val;
            if (ps == 0)      val = pv;
            else if (ps <= 5) val = sinpif(pv * (float)(1 << (ps - 1)));
            else              val = cospif(pv * (float)(1 << (ps - 6)));
            s_ca[tid] = val;
        }
        __syncthreads();

        // ---- dot product: thread owns output dim tid, coalesced L1-resident Wt loads ----
        float h = __ldg(ctx_b + tid);
        const float* wt = g_Wt + tid;
        int k = 0;
#pragma unroll
        for (; k + 8 <= 143; k += 8) {
            const float w0 = wt[(k + 0) * 256], w1 = wt[(k + 1) * 256];
            const float w2 = wt[(k + 2) * 256], w3 = wt[(k + 3) * 256];
            const float w4 = wt[(k + 4) * 256], w5 = wt[(k + 5) * 256];
            const float w6 = wt[(k + 6) * 256], w7 = wt[(k + 7) * 256];
            h = fmaf(s_ca[k + 0], w0, h); h = fmaf(s_ca[k + 1], w1, h);
            h = fmaf(s_ca[k + 2], w2, h); h = fmaf(s_ca[k + 3], w3, h);
            h = fmaf(s_ca[k + 4], w4, h); h = fmaf(s_ca[k + 5], w5, h);
            h = fmaf(s_ca[k + 6], w6, h); h = fmaf(s_ca[k + 7], w7, h);
        }
#pragma unroll
        for (; k < 143; ++k)
            h = fmaf(s_ca[k], wt[k * 256], h);

        // ---- block LayerNorm over 256 dims ----
        float s1 = h, s2 = h * h;
#pragma unroll
        for (int o = 16; o; o >>= 1) {
            s1 += __shfl_xor_sync(0xffffffffu, s1, o);
            s2 += __shfl_xor_sync(0xffffffffu, s2, o);
        }
        if (lane == 0) { s_red[wid * 2] = s1; s_red[wid * 2 + 1] = s2; }
        __syncthreads();
        if (tid == 0) {
            float t1 = 0.f, t2 = 0.f;
#pragma unroll
            for (int w = 0; w < 8; ++w) { t1 += s_red[w * 2]; t2 += s_red[w * 2 + 1]; }
            const float mu  = t1 * (1.f / 256.f);
            const float var = t2 * (1.f / 256.f) - mu * mu;
            s_ms[0] = mu;
            s_ms[1] = rsqrtf(var + 1e-5f);
        }
        __syncthreads();
        const float v = fmaf((h - s_ms[0]) * s_ms[1], __ldg(ctx_g + tid), __ldg(ctx_be + tid));
        out[(size_t)t * 256 + tid] += fmaxf(v, 0.f);
    }
}

} // namespace

extern "C" void kernel_launch(void* const* d_in, const int* in_sizes, int n_in,
                              void* d_out, int out_size)
{
    const int tokens = in_sizes[0];   // N*S

    transpose_ctx_kernel<<<143, 256>>>((const float*)d_in[21]);

    poker_main_kernel<<<NB_MAIN, 256>>>(
        (const int*)  d_in[0],   // token_ids
        (const int*)  d_in[1],   // token_streets
        (const int*)  d_in[2],   // card_ranks
        (const int*)  d_in[3],   // card_suits
        (const int*)  d_in[4],   // action_actors
        (const float*)d_in[5],   // action_legal_masks
        (const float*)d_in[6],   // context_features
        (const float*)d_in[7],   // base_emb
        (const float*)d_in[8],   // street_emb
        (const float*)d_in[9],   // rank_emb
        (const float*)d_in[10],  // suit_emb
        (const float*)d_in[11],  // actor_emb
        (const float*)d_in[12],  // atype_emb
        (const float*)d_in[13],  // legal_W
        (const float*)d_in[14],  // legal_b
        (const float*)d_in[15],  // legal_g
        (const float*)d_in[16],  // legal_beta
        (const float*)d_in[17],  // game_W
        (const float*)d_in[18],  // game_b
        (const float*)d_in[19],  // game_g
        (const float*)d_in[20],  // game_beta
        (float*)d_out,
        tokens);

    const int nb_ctx = (tokens + CTX_SEG - 1) / CTX_SEG;
    poker_ctx_kernel<<<nb_ctx, 256>>>(
        (const int*)  d_in[0],   // token_ids
        (const float*)d_in[6],   // context_features
        (const float*)d_in[22],  // ctx_b
        (const float*)d_in[23],  // ctx_g
        (const float*)d_in[24],  // ctx_beta
        (float*)d_out,
        tokens);
}